// round 10
// baseline (speedup 1.0000x reference)
#include <cuda_runtime.h>
#include <cstdint>

// One persistent kernel, 148 CTAs x 1024 threads.
// FAST PATH (verified per-run): indices follow flat(i) = (F0 + i*P) mod T,
//   row = flat >> shiftU, col = flat & mask  (units = power of two).
//   Phase 1: transpose x  +  fused verify + DETERMINISTIC scatter (slot
//   j = i>>shiftU, col = flat&mask -> no atomics, coalesced kv read).
//   barrier; compute: coalesced entry loads + prefetch + shuffle broadcast.
// FALLBACK (any mismatch): atomic scatter + 2nd barrier, same compute loop.
#define GRID  148
#define TPB   1024
#define NWARP (TPB / 32)
#define MAX_UNITS 2048
#define CAP       512
#define MAX_INPUT 30016

__device__ float     g_xT[MAX_INPUT * 32];            // x transposed: [input_dim][32]
__device__ long long g_entries[MAX_UNITS * CAP];      // {val_bits:32 | (row<<5):32}
__device__ int       g_cursor[MAX_UNITS];             // fallback only (self-cleaning)
__device__ int       g_cta_ok[GRID];                  // per-CTA verification flags
__device__ unsigned  g_bar;                           // monotone barrier counter

__device__ __forceinline__ void grid_barrier() {
    __syncthreads();
    if (threadIdx.x == 0) {
        __threadfence();
        unsigned arrive = atomicAdd(&g_bar, 1u) + 1u;
        unsigned rem = arrive % GRID;
        unsigned target = rem ? (arrive + (GRID - rem)) : arrive;
        unsigned v;
        do {
            asm volatile("ld.acquire.gpu.global.u32 %0, [%1];" : "=r"(v) : "l"(&g_bar));
        } while ((int)(v - target) < 0);
    }
    __syncthreads();
}

__global__ void __launch_bounds__(TPB, 1)
fused_kernel(const float* __restrict__ x,
             const float* __restrict__ kv,
             const float* __restrict__ bias,
             const int*   __restrict__ ind,
             float* __restrict__ out,
             int nnz, int units, int batch, int input_dim)
{
    __shared__ __align__(16) float s_part[NWARP][32];
    const int tid  = threadIdx.x;
    const int bid  = blockIdx.x;
    const int lane = tid & 31;
    const int warp = tid >> 5;
    const int gwarp = bid * NWARP + warp;
    const int2* ind2 = (const int2*)ind;
    const int4* ind4 = (const int4*)ind;

    // ---- dtype detect (int64 LE => odd 32-bit words all 0) --------------------
    int nchk = nnz < TPB ? nnz : TPB;
    int vv = (tid < nchk) ? ind[2 * tid + 1] : 0;
    const int is64 = __syncthreads_or(vv != 0) ? 0 : 1;

    // ---- derive linear-congruence model from first two entries ----------------
    int r0d, c0d, r1d, c1d;
    if (is64) { r0d = ind[0]; c0d = ind[2]; r1d = ind[4]; c1d = ind[6]; }
    else      { r0d = ind[0]; c0d = ind[1]; r1d = ind[2]; c1d = ind[3]; }
    const unsigned T  = (unsigned)input_dim * (unsigned)units;
    const bool upot   = units > 0 && (units & (units - 1)) == 0;
    const int shiftU  = __popc(units - 1);
    const unsigned F0 = (unsigned)r0d * (unsigned)units + (unsigned)c0d;
    const unsigned F1 = (unsigned)r1d * (unsigned)units + (unsigned)c1d;
    const unsigned P  = (F1 + T - (T ? (F0 % T) : 0u)) % (T ? T : 1u);
    const unsigned mask = (unsigned)units - 1;
    const unsigned d  = P & mask;
    bool structural = upot && (d & 1u) && nnz >= 2 && units <= MAX_UNITS
                      && F0 < T && F1 < T && batch <= 32
                      && input_dim <= MAX_INPUT
                      && (((unsigned)nnz - 1u) >> shiftU) < CAP;
    if (structural) {                 // uniqueness: period T/gcd(P,T) must cover nnz
        unsigned a = P, b = T;
        while (b) { unsigned t = a % b; a = b; b = t; }     // a = gcd(P,T) (P>0)
        structural = (a != 0) && (T / a >= (unsigned)nnz);
    }

    // ========== Phase 1a: transpose x -> g_xT[input][32]  (no smem/syncs) ======
    const int idim = input_dim <= MAX_INPUT ? input_dim : MAX_INPUT;
    if ((idim & 3) == 0) {
        int nblk = idim >> 3;
        const bool have_row = (lane < batch);
        const float4* xb = (const float4*)(x + (size_t)lane * input_dim);
        for (int blk = gwarp; blk < nblk; blk += GRID * NWARP) {
            int i0 = blk * 8;
            float4 v0 = make_float4(0.f, 0.f, 0.f, 0.f), v1 = v0;
            if (have_row) { v0 = xb[i0 >> 2]; v1 = xb[(i0 >> 2) + 1]; }
            float* dst = g_xT + i0 * 32 + lane;
            dst[0]   = v0.x; dst[32]  = v0.y; dst[64]  = v0.z; dst[96]  = v0.w;
            dst[128] = v1.x; dst[160] = v1.y; dst[192] = v1.z; dst[224] = v1.w;
        }
        for (int i = nblk * 8 + gwarp; i < idim; i += GRID * NWARP)
            g_xT[i * 32 + lane] = have_row ? x[(size_t)lane * input_dim + i] : 0.f;
    } else {
        for (int i = gwarp; i < idim; i += GRID * NWARP)
            g_xT[i * 32 + lane] = (lane < batch) ? x[(size_t)lane * input_dim + i] : 0.f;
    }

    // ========== Phase 1b: fused verify + deterministic scatter (coalesced) =====
    bool ok = structural;
    if (structural) {
        const unsigned S = GRID * TPB;
        unsigned i = (unsigned)(bid * TPB + tid);
        if (i < (unsigned)nnz) {
            unsigned flat = (unsigned)((F0 + (unsigned long long)i * P) % T);
            unsigned Dv   = (unsigned)(((unsigned long long)S * P) % T);
            for (; i < (unsigned)nnz; i += S) {
                int r, c;
                if (is64) { int4 w = ind4[i]; r = w.x; c = w.z; }
                else      { int2 w = ind2[i]; r = w.x; c = w.y; }
                float val = kv[i];                       // coalesced
                ok = ok && ((unsigned)c < (unsigned)units)
                        && ((unsigned)r < (unsigned)input_dim)
                        && (flat == (((unsigned)r << shiftU) + (unsigned)c));
                unsigned cc = flat & mask;               // model-derived (in-bounds)
                unsigned jj = i >> shiftU;               // < CAP by structural guard
                g_entries[cc * CAP + jj] =
                    ((long long)__float_as_int(val) << 32)
                    | (unsigned)((flat >> shiftU) << 5);
                flat += Dv; if (flat >= T) flat -= T;
            }
        }
    }
    int cta_ok = __syncthreads_and(ok ? 1 : 0);
    if (tid == 0) g_cta_ok[bid] = cta_ok;

    grid_barrier();

    int myflag = (tid < GRID) ? g_cta_ok[tid] : 1;
    const int all_ok = __syncthreads_and(myflag);

    const int team = gwarp >> 1;
    const int half = gwarp & 1;
    const bool active = (team < units);

    // ========== FALLBACK scatter (only when model rejected) ====================
    if (!all_ok) {
        if (is64) {
            for (int i = bid * TPB + tid; i < nnz; i += GRID * TPB) {
                int4 w = ind4[i];
                float val = kv[i];
                if ((unsigned)w.z < (unsigned)units) {
                    int pos = atomicAdd(&g_cursor[w.z], 1);
                    if (pos < CAP)
                        g_entries[w.z * CAP + pos] =
                            ((long long)__float_as_int(val) << 32) | (unsigned)(w.x << 5);
                }
            }
        } else {
            for (int i = bid * TPB + tid; i < nnz; i += GRID * TPB) {
                int2 w = ind2[i];
                float val = kv[i];
                if ((unsigned)w.y < (unsigned)units) {
                    int pos = atomicAdd(&g_cursor[w.y], 1);
                    if (pos < CAP)
                        g_entries[w.y * CAP + pos] =
                            ((long long)__float_as_int(val) << 32) | (unsigned)(w.x << 5);
                }
            }
        }
        grid_barrier();
    }

    // ========== Unified compute: coalesced entries + prefetch + shuffles =======
    int n = 0;
    if (active) {
        if (all_ok) {
            unsigned xinv = d;                            // d^{-1} mod 2^32 (Newton)
            #pragma unroll
            for (int it = 0; it < 5; it++) xinv = xinv * (2u - d * xinv);
            unsigned cdelta = (((unsigned)team + (unsigned)units) - (F0 & mask)) & mask;
            unsigned i0 = (xinv * cdelta) & mask;
            n = (i0 < (unsigned)nnz)
                ? (int)((((unsigned)nnz - 1u - i0) >> shiftU) + 1u) : 0;
        } else {
            n = g_cursor[team]; n = n < CAP ? n : CAP;
        }
    }
    const long long* ent = g_entries + (active ? team : 0) * CAP;

    float a0 = 0.f, a1 = 0.f, a2 = 0.f, a3 = 0.f;
    {
        int k0 = half * 32;
        long long enext = (k0 + lane < n) ? ent[k0 + lane] : 0LL;
        for (; k0 < n; k0 += 64) {
            long long ec = enext;
            int kn = k0 + 64;
            enext = (kn + lane < n) ? ent[kn + lane] : 0LL;   // prefetch next chunk
            unsigned r32 = (unsigned)(ec & 0xffffffffLL);
            float    val = __int_as_float((int)(ec >> 32));
#pragma unroll
            for (int j = 0; j < 32; j += 4) {
                float    v0 = __shfl_sync(0xffffffffu, val, j + 0);
                unsigned q0 = __shfl_sync(0xffffffffu, r32, j + 0);
                float    v1 = __shfl_sync(0xffffffffu, val, j + 1);
                unsigned q1 = __shfl_sync(0xffffffffu, r32, j + 1);
                float    v2 = __shfl_sync(0xffffffffu, val, j + 2);
                unsigned q2 = __shfl_sync(0xffffffffu, r32, j + 2);
                float    v3 = __shfl_sync(0xffffffffu, val, j + 3);
                unsigned q3 = __shfl_sync(0xffffffffu, r32, j + 3);
                a0 = fmaf(v0, g_xT[q0 + lane], a0);
                a1 = fmaf(v1, g_xT[q1 + lane], a1);
                a2 = fmaf(v2, g_xT[q2 + lane], a2);
                a3 = fmaf(v3, g_xT[q3 + lane], a3);
            }
        }
    }
    float acc = (a0 + a1) + (a2 + a3);
    if (half) s_part[warp][lane] = acc;
    __syncthreads();
    if (!half && active) {
        acc += s_part[warp + 1][lane];
        if (lane < batch)
            out[lane * units + team] = tanhf(acc + bias[team]);
        if (!all_ok && lane == 0) g_cursor[team] = 0;     // self-clean (fallback)
    }
}

extern "C" void kernel_launch(void* const* d_in, const int* in_sizes, int n_in,
                              void* d_out, int out_size) {
    const float* x    = (const float*)d_in[0];
    const float* kv   = (const float*)d_in[1];
    const float* bias = (const float*)d_in[2];
    const int*   ind  = (const int*)d_in[3];
    float* out = (float*)d_out;

    int nnz       = in_sizes[1];
    int units     = in_sizes[2];
    int batch     = out_size / units;          // 32
    int input_dim = in_sizes[0] / batch;       // 30000

    fused_kernel<<<GRID, TPB>>>(x, kv, bias, ind, out,
                                nnz, units, batch, input_dim);
}

// round 11
// speedup vs baseline: 1.1064x; 1.1064x over previous
#include <cuda_runtime.h>
#include <cstdint>

// One persistent kernel, 148 CTAs x 1024 threads.
// FAST PATH (verified per-run): indices follow flat(i) = (F0 + i*P) mod T,
//   row = flat >> shiftU, col = flat & mask  (units = power of two).
//   Phase 1: transpose x  +  fused verify + DETERMINISTIC scatter (no atomics).
//   barrier; compute: f32x2 dual-batch FMA, uniform-LDG broadcast (no shuffles).
// FALLBACK (any mismatch): atomic scatter + 2nd barrier, same compute loop.
#define GRID  148
#define TPB   1024
#define NWARP (TPB / 32)
#define MAX_UNITS 2048
#define CAP       512
#define MAX_INPUT 30016

__device__ float     g_xT[MAX_INPUT * 32];            // x transposed: [input_dim][32]
__device__ long long g_entries[MAX_UNITS * CAP];      // {val_bits:32 | (row<<5):32}
__device__ int       g_cursor[MAX_UNITS];             // fallback only (self-cleaning)
__device__ int       g_cta_ok[GRID];                  // per-CTA verification flags
__device__ unsigned  g_bar;                           // monotone barrier counter

__device__ __forceinline__ void grid_barrier() {
    __syncthreads();
    if (threadIdx.x == 0) {
        __threadfence();
        unsigned arrive = atomicAdd(&g_bar, 1u) + 1u;
        unsigned rem = arrive % GRID;
        unsigned target = rem ? (arrive + (GRID - rem)) : arrive;
        unsigned v;
        do {
            asm volatile("ld.acquire.gpu.global.u32 %0, [%1];" : "=r"(v) : "l"(&g_bar));
        } while ((int)(v - target) < 0);
    }
    __syncthreads();
}

__global__ void __launch_bounds__(TPB, 1)
fused_kernel(const float* __restrict__ x,
             const float* __restrict__ kv,
             const float* __restrict__ bias,
             const int*   __restrict__ ind,
             float* __restrict__ out,
             int nnz, int units, int batch, int input_dim)
{
    __shared__ __align__(16) unsigned long long s_part[NWARP][16];
    const int tid  = threadIdx.x;
    const int bid  = blockIdx.x;
    const int lane = tid & 31;
    const int warp = tid >> 5;
    const int gwarp = bid * NWARP + warp;
    const int2* ind2 = (const int2*)ind;
    const int4* ind4 = (const int4*)ind;

    // ---- dtype detect (int64 LE => odd 32-bit words all 0) --------------------
    int nchk = nnz < TPB ? nnz : TPB;
    int vv = (tid < nchk) ? ind[2 * tid + 1] : 0;
    const int is64 = __syncthreads_or(vv != 0) ? 0 : 1;

    // ---- derive linear-congruence model from first two entries ----------------
    int r0d, c0d, r1d, c1d;
    if (is64) { r0d = ind[0]; c0d = ind[2]; r1d = ind[4]; c1d = ind[6]; }
    else      { r0d = ind[0]; c0d = ind[1]; r1d = ind[2]; c1d = ind[3]; }
    const unsigned T  = (unsigned)input_dim * (unsigned)units;
    const bool upot   = units > 0 && (units & (units - 1)) == 0;
    const int shiftU  = __popc(units - 1);
    const unsigned F0 = (unsigned)r0d * (unsigned)units + (unsigned)c0d;
    const unsigned F1 = (unsigned)r1d * (unsigned)units + (unsigned)c1d;
    const unsigned P  = (F1 + T - (T ? (F0 % T) : 0u)) % (T ? T : 1u);
    const unsigned mask = (unsigned)units - 1;
    const unsigned d  = P & mask;
    bool structural = upot && (d & 1u) && nnz >= 2 && units <= MAX_UNITS
                      && F0 < T && F1 < T && batch <= 32
                      && input_dim <= MAX_INPUT
                      && (((unsigned)nnz - 1u) >> shiftU) < CAP;
    if (structural) {                 // uniqueness: period T/gcd(P,T) must cover nnz
        unsigned a = P, b = T;
        while (b) { unsigned t = a % b; a = b; b = t; }     // a = gcd(P,T) (P>0)
        structural = (a != 0) && (T / a >= (unsigned)nnz);
    }

    // ========== Phase 1a: transpose x -> g_xT[input][32]  (no smem/syncs) ======
    const int idim = input_dim <= MAX_INPUT ? input_dim : MAX_INPUT;
    if ((idim & 3) == 0) {
        int nblk = idim >> 3;
        const bool have_row = (lane < batch);
        const float4* xb = (const float4*)(x + (size_t)lane * input_dim);
        for (int blk = gwarp; blk < nblk; blk += GRID * NWARP) {
            int i0 = blk * 8;
            float4 v0 = make_float4(0.f, 0.f, 0.f, 0.f), v1 = v0;
            if (have_row) { v0 = xb[i0 >> 2]; v1 = xb[(i0 >> 2) + 1]; }
            float* dst = g_xT + i0 * 32 + lane;
            dst[0]   = v0.x; dst[32]  = v0.y; dst[64]  = v0.z; dst[96]  = v0.w;
            dst[128] = v1.x; dst[160] = v1.y; dst[192] = v1.z; dst[224] = v1.w;
        }
        for (int i = nblk * 8 + gwarp; i < idim; i += GRID * NWARP)
            g_xT[i * 32 + lane] = have_row ? x[(size_t)lane * input_dim + i] : 0.f;
    } else {
        for (int i = gwarp; i < idim; i += GRID * NWARP)
            g_xT[i * 32 + lane] = (lane < batch) ? x[(size_t)lane * input_dim + i] : 0.f;
    }

    // ========== Phase 1b: fused verify + deterministic scatter (coalesced) =====
    bool ok = structural;
    if (structural) {
        const unsigned S = GRID * TPB;
        unsigned i = (unsigned)(bid * TPB + tid);
        if (i < (unsigned)nnz) {
            unsigned flat = (unsigned)((F0 + (unsigned long long)i * P) % T);
            unsigned Dv   = (unsigned)(((unsigned long long)S * P) % T);
            for (; i < (unsigned)nnz; i += S) {
                int r, c;
                if (is64) { int4 w = ind4[i]; r = w.x; c = w.z; }
                else      { int2 w = ind2[i]; r = w.x; c = w.y; }
                float val = kv[i];                       // coalesced
                ok = ok && ((unsigned)c < (unsigned)units)
                        && ((unsigned)r < (unsigned)input_dim)
                        && (flat == (((unsigned)r << shiftU) + (unsigned)c));
                unsigned cc = flat & mask;               // model-derived (in-bounds)
                unsigned jj = i >> shiftU;               // < CAP by structural guard
                g_entries[cc * CAP + jj] =
                    ((long long)__float_as_int(val) << 32)
                    | (unsigned)((flat >> shiftU) << 5);
                flat += Dv; if (flat >= T) flat -= T;
            }
        }
    }
    int cta_ok = __syncthreads_and(ok ? 1 : 0);
    if (tid == 0) g_cta_ok[bid] = cta_ok;

    grid_barrier();

    int myflag = (tid < GRID) ? g_cta_ok[tid] : 1;
    const int all_ok = __syncthreads_and(myflag);

    const int team = gwarp >> 1;
    const int half = gwarp & 1;
    const bool active = (team < units);

    // ========== FALLBACK scatter (only when model rejected) ====================
    if (!all_ok) {
        if (is64) {
            for (int i = bid * TPB + tid; i < nnz; i += GRID * TPB) {
                int4 w = ind4[i];
                float val = kv[i];
                if ((unsigned)w.z < (unsigned)units) {
                    int pos = atomicAdd(&g_cursor[w.z], 1);
                    if (pos < CAP)
                        g_entries[w.z * CAP + pos] =
                            ((long long)__float_as_int(val) << 32) | (unsigned)(w.x << 5);
                }
            }
        } else {
            for (int i = bid * TPB + tid; i < nnz; i += GRID * TPB) {
                int2 w = ind2[i];
                float val = kv[i];
                if ((unsigned)w.y < (unsigned)units) {
                    int pos = atomicAdd(&g_cursor[w.y], 1);
                    if (pos < CAP)
                        g_entries[w.y * CAP + pos] =
                            ((long long)__float_as_int(val) << 32) | (unsigned)(w.x << 5);
                }
            }
        }
        grid_barrier();
    }

    // ========== Compute: f32x2 dual-batch, uniform-LDG broadcast ===============
    // Warp = half of a 2-warp team per column. Half-warps process different
    // entries (hsel), lane&15 owns batch pair (2b, 2b+1) as one f32x2.
    int n = 0;
    if (active) {
        if (all_ok) {
            unsigned xinv = d;                            // d^{-1} mod 2^32 (Newton)
            #pragma unroll
            for (int it = 0; it < 5; it++) xinv = xinv * (2u - d * xinv);
            unsigned cdelta = (((unsigned)team + (unsigned)units) - (F0 & mask)) & mask;
            unsigned i0 = (xinv * cdelta) & mask;
            n = (i0 < (unsigned)nnz)
                ? (int)((((unsigned)nnz - 1u - i0) >> shiftU) + 1u) : 0;
        } else {
            n = g_cursor[team]; n = n < CAP ? n : CAP;
        }
    }
    const int hh   = (n + 1) >> 1;
    const int j0   = half ? hh : 0;
    const int jend = half ? n  : hh;
    const int cnt  = jend - j0;
    const long long* ent = g_entries + (size_t)(active ? team : 0) * CAP + j0;

    const int hsel  = lane >> 4;                      // 0/1: which entry of the pair
    const int bpair = lane & 15;                      // batch pair index
    const float* xbase = g_xT + 2 * bpair;

    unsigned long long acc0 = 0ULL, acc1 = 0ULL;
    for (int t = hsel; t < cnt; t += 4) {
        long long eA = ent[t];                        // uniform per half-warp
        long long eB = (t + 2 < cnt) ? ent[t + 2] : 0LL;
        unsigned rA = (unsigned)eA; float vA = __int_as_float((int)(eA >> 32));
        unsigned rB = (unsigned)eB; float vB = __int_as_float((int)(eB >> 32));
        unsigned long long xA = *(const unsigned long long*)(xbase + rA);
        unsigned long long xB = *(const unsigned long long*)(xbase + rB);
        unsigned long long dA, dB;
        asm("mov.b64 %0, {%1, %1};" : "=l"(dA) : "r"(__float_as_uint(vA)));
        asm("mov.b64 %0, {%1, %1};" : "=l"(dB) : "r"(__float_as_uint(vB)));
        asm("fma.rn.f32x2 %0, %1, %2, %0;" : "+l"(acc0) : "l"(dA), "l"(xA));
        asm("fma.rn.f32x2 %0, %1, %2, %0;" : "+l"(acc1) : "l"(dB), "l"(xB));
    }
    unsigned long long acc;
    asm("add.rn.f32x2 %0, %1, %2;" : "=l"(acc) : "l"(acc0), "l"(acc1));
    {   // combine the two half-warps (same batch pair, different entries)
        unsigned long long o = __shfl_xor_sync(0xffffffffu, acc, 16);
        asm("add.rn.f32x2 %0, %0, %1;" : "+l"(acc) : "l"(o));
    }
    if (half && hsel == 0) s_part[warp][bpair] = acc; // odd warp publishes
    __syncthreads();
    if (!half && active && hsel == 0) {
        unsigned long long o = s_part[warp + 1][bpair];
        asm("add.rn.f32x2 %0, %0, %1;" : "+l"(acc) : "l"(o));
        unsigned alo = (unsigned)acc, ahi = (unsigned)(acc >> 32);
        float bz = bias[team];
        int b0 = 2 * bpair, b1 = b0 + 1;
        if (b0 < batch) out[b0 * units + team] = tanhf(__uint_as_float(alo) + bz);
        if (b1 < batch) out[b1 * units + team] = tanhf(__uint_as_float(ahi) + bz);
    }
    if (!all_ok && !half && active && lane == 0)
        g_cursor[team] = 0;                           // self-clean (fallback)
}

extern "C" void kernel_launch(void* const* d_in, const int* in_sizes, int n_in,
                              void* d_out, int out_size) {
    const float* x    = (const float*)d_in[0];
    const float* kv   = (const float*)d_in[1];
    const float* bias = (const float*)d_in[2];
    const int*   ind  = (const int*)d_in[3];
    float* out = (float*)d_out;

    int nnz       = in_sizes[1];
    int units     = in_sizes[2];
    int batch     = out_size / units;          // 32
    int input_dim = in_sizes[0] / batch;       // 30000

    fused_kernel<<<GRID, TPB>>>(x, kv, bias, ind, out,
                                nnz, units, batch, input_dim);
}